// round 1
// baseline (speedup 1.0000x reference)
#include <cuda_runtime.h>

#define NQ 6
#define NF 4
#define NL 2
#define NS 64   // 2^NQ amplitudes

// trig of weights / ancilla, precomputed once per launch by prep_kernel
__device__ float g_wc[NL * NQ];
__device__ float g_ws[NL * NQ];
__device__ float g_ac[2];
__device__ float g_as[2];

__global__ void prep_kernel(const float* __restrict__ w, const float* __restrict__ ab) {
    int i = threadIdx.x;
    if (i < NL * NQ) {
        g_wc[i] = cosf(0.5f * w[i]);
        g_ws[i] = sinf(0.5f * w[i]);
    }
    if (i < 2) {
        g_ac[i] = cosf(0.5f * ab[i]);
        g_as[i] = sinf(0.5f * ab[i]);
    }
}

// One thread = one sample. State (64 complex) lives in registers as r[64], im[64].
// Qubit w occupies bit (5-w) of the amplitude index (PennyLane wire order).
__global__ void __launch_bounds__(128) qsim_kernel(const float* __restrict__ x,
                                                   float* __restrict__ out,
                                                   int B) {
    int b = blockIdx.x * blockDim.x + threadIdx.x;
    if (b >= B) return;

    float4 xv = reinterpret_cast<const float4*>(x)[b];

    float xc[NF], xs[NF];
    __sincosf(0.5f * xv.x, &xs[0], &xc[0]);
    __sincosf(0.5f * xv.y, &xs[1], &xc[1]);
    __sincosf(0.5f * xv.z, &xs[2], &xc[2]);
    __sincosf(0.5f * xv.w, &xs[3], &xc[3]);

    // Kronecker build of initial product-state magnitudes.
    // RX(x)|0> = cos|0> + (-i sin)|1>  -> magnitude cos/sin, phase (-i)^k,
    // k = #qubits(0..3) in |1>.
    float p2[4];
    p2[0] = xc[0] * xc[1];
    p2[1] = xc[0] * xs[1];
    p2[2] = xs[0] * xc[1];
    p2[3] = xs[0] * xs[1];

    float p4[16];
#pragma unroll
    for (int n = 0; n < 16; n++) {
        float f2 = (n & 2) ? xs[2] : xc[2];
        float f3 = (n & 1) ? xs[3] : xc[3];
        p4[n] = p2[n >> 2] * f2 * f3;
    }

    // RY(ancilla_bias)|0> = (cos, sin): purely real
    float anc[4];
#pragma unroll
    for (int m = 0; m < 4; m++) {
        float a4 = (m & 2) ? g_as[0] : g_ac[0];
        float a5 = (m & 1) ? g_as[1] : g_ac[1];
        anc[m] = a4 * a5;
    }

    float r[NS], im[NS];
#pragma unroll
    for (int idx = 0; idx < NS; idx++) {
        const int n = idx >> 2;           // bits of qubits 0..3
        const int m = idx & 3;            // bits of qubits 4,5
        const int k = ((n & 1) + ((n >> 1) & 1) + ((n >> 2) & 1) + ((n >> 3) & 1)) & 3;
        float mag = p4[n] * anc[m];
        // (-i)^k phase
        r[idx]  = (k == 0) ? mag : ((k == 2) ? -mag : 0.0f);
        im[idx] = (k == 1) ? -mag : ((k == 3) ? mag : 0.0f);
    }

    // Entangling layers: CNOT ring then RY rotations. All real ops, applied
    // independently to r[] and im[]. Fully unrolled -> CNOT = register renames.
#pragma unroll
    for (int l = 0; l < NL; l++) {
        // CNOT ring: control w, target (w+1)%6
#pragma unroll
        for (int w = 0; w < NQ; w++) {
            const int cb = 1 << (5 - w);
            const int tb = 1 << (5 - ((w + 1) % NQ));
#pragma unroll
            for (int idx = 0; idx < NS; idx++) {
                if ((idx & cb) && !(idx & tb)) {
                    const int j = idx ^ tb;
                    float t;
                    t = r[idx];  r[idx]  = r[j];  r[j]  = t;
                    t = im[idx]; im[idx] = im[j]; im[j] = t;
                }
            }
        }
        // RY(weights[l][w]) on each qubit
#pragma unroll
        for (int w = 0; w < NQ; w++) {
            const float cc = g_wc[l * NQ + w];
            const float ss = g_ws[l * NQ + w];
            const int tb = 1 << (5 - w);
#pragma unroll
            for (int idx = 0; idx < NS; idx++) {
                if (!(idx & tb)) {
                    const int j = idx | tb;
                    float r0 = r[idx], r1 = r[j];
                    r[idx] = cc * r0 - ss * r1;
                    r[j]   = ss * r0 + cc * r1;
                    float i0 = im[idx], i1 = im[j];
                    im[idx] = cc * i0 - ss * i1;
                    im[j]   = ss * i0 + cc * i1;
                }
            }
        }
    }

    // <Z_w> for w in 0..3:  z_w = total - 2 * sum_{bit_w(idx)=1} p(idx)
    float tot = 0.0f;
    float s1[NF] = {0.0f, 0.0f, 0.0f, 0.0f};
#pragma unroll
    for (int idx = 0; idx < NS; idx++) {
        float p = r[idx] * r[idx] + im[idx] * im[idx];
        tot += p;
#pragma unroll
        for (int w = 0; w < NF; w++) {
            if (idx & (1 << (5 - w))) s1[w] += p;
        }
    }

    float4 o;
    o.x = tot - 2.0f * s1[0];
    o.y = tot - 2.0f * s1[1];
    o.z = tot - 2.0f * s1[2];
    o.w = tot - 2.0f * s1[3];
    reinterpret_cast<float4*>(out)[b] = o;
}

extern "C" void kernel_launch(void* const* d_in, const int* in_sizes, int n_in,
                              void* d_out, int out_size) {
    const float* x  = (const float*)d_in[0];   // (B, 4) float32
    const float* w  = (const float*)d_in[1];   // (2, 6) float32
    const float* ab = (const float*)d_in[2];   // (2,)   float32

    prep_kernel<<<1, 32>>>(w, ab);

    int B = in_sizes[0] / NF;
    int threads = 128;
    int blocks = (B + threads - 1) / threads;
    qsim_kernel<<<blocks, threads>>>(x, (float*)d_out, B);
}

// round 4
// speedup vs baseline: 1.3145x; 1.3145x over previous
#include <cuda_runtime.h>

#define NQ 6
#define NF 4
#define NL 2
#define NS 64

// ---------- compile-time CNOT permutation tracking ----------
// Logical amplitude L[i] lives in physical register V[m[i]].
// CNOT(c,t): newL[i] = L[f(i)], f flips target bit when control bit set,
// so m' = m ∘ f. Qubit w occupies bit (5-w) (PennyLane wire order).
__host__ __device__ constexpr int cnot_map(int i, int c, int t) {
    return (i & (1 << (5 - c))) ? (i ^ (1 << (5 - t))) : i;
}

struct Perm { int m[NS]; };

__host__ __device__ constexpr Perm identity_perm() {
    Perm p{};
    for (int i = 0; i < NS; i++) p.m[i] = i;
    return p;
}

__host__ __device__ constexpr Perm ring_perm(Perm p) {
    for (int w = 0; w < NQ; w++) {
        Perm q{};
        for (int i = 0; i < NS; i++)
            q.m[i] = p.m[cnot_map(i, w, (w + 1) % NQ)];
        p = q;
    }
    return p;
}

// ---------- packed f32x2 helpers (sm_100+) ----------
typedef unsigned long long u64;

__device__ __forceinline__ u64 pk(float lo, float hi) {
    u64 r;
    asm("mov.b64 %0, {%1, %2};" : "=l"(r) : "f"(lo), "f"(hi));
    return r;
}
__device__ __forceinline__ void upk(u64 v, float& lo, float& hi) {
    asm("mov.b64 {%0, %1}, %2;" : "=f"(lo), "=f"(hi) : "l"(v));
}
__device__ __forceinline__ u64 f2mul(u64 a, u64 b) {
    u64 d;
    asm("mul.rn.f32x2 %0, %1, %2;" : "=l"(d) : "l"(a), "l"(b));
    return d;
}
__device__ __forceinline__ u64 f2fma(u64 a, u64 b, u64 c) {
    u64 d;
    asm("fma.rn.f32x2 %0, %1, %2, %3;" : "=l"(d) : "l"(a), "l"(b), "l"(c));
    return d;
}

// One thread = one sample. Packed state: V[idx] = (Re, Im) in one 64-bit reg pair.
__global__ void __launch_bounds__(64) qsim_kernel(const float* __restrict__ x,
                                                  const float* __restrict__ wts,
                                                  const float* __restrict__ ab,
                                                  float* __restrict__ out) {
    // CNOT-ring permutations, constant-folded at compile time (constexpr locals
    // are valid in device code, unlike namespace-scope constexpr objects).
    constexpr Perm P1 = ring_perm(identity_perm());  // after layer-1 ring
    constexpr Perm P2 = ring_perm(P1);               // after layer-2 ring

    const int b = blockIdx.x * blockDim.x + threadIdx.x;

    // ---- per-thread trig (MUFU pipe, overlaps with FMA work) ----
    float4 xv = reinterpret_cast<const float4*>(x)[b];
    float xc[NF], xs[NF];
    __sincosf(0.5f * xv.x, &xs[0], &xc[0]);
    __sincosf(0.5f * xv.y, &xs[1], &xc[1]);
    __sincosf(0.5f * xv.z, &xs[2], &xc[2]);
    __sincosf(0.5f * xv.w, &xs[3], &xc[3]);

    float wc[NL * NQ], ws[NL * NQ];
    const float4* w4 = reinterpret_cast<const float4*>(wts);
    float4 wa = w4[0], wb = w4[1], wcv = w4[2];
    const float wv[12] = {wa.x, wa.y, wa.z, wa.w, wb.x, wb.y, wb.z, wb.w,
                          wcv.x, wcv.y, wcv.z, wcv.w};
#pragma unroll
    for (int i = 0; i < NL * NQ; i++) __sincosf(0.5f * wv[i], &ws[i], &wc[i]);

    float ac0, as0, ac1, as1;
    __sincosf(0.5f * ab[0], &as0, &ac0);
    __sincosf(0.5f * ab[1], &as1, &ac1);

    // ---- initial product state ----
    // RX(x)|0> per encoded qubit -> magnitude Kronecker product, phase (-i)^k,
    // k = popcount over qubits 0..3. Fold the overall sign into the magnitude.
    float p2[4];
    p2[0] = xc[0] * xc[1];
    p2[1] = xc[0] * xs[1];
    p2[2] = xs[0] * xc[1];
    p2[3] = xs[0] * xs[1];

    float p4s[16];  // signed magnitudes over qubits 0..3
#pragma unroll
    for (int n = 0; n < 16; n++) {
        const int k = ((n & 1) + ((n >> 1) & 1) + ((n >> 2) & 1) + ((n >> 3) & 1)) & 3;
        float f2 = (n & 2) ? xs[2] : xc[2];
        float f3 = (n & 1) ? xs[3] : xc[3];
        float v = p2[n >> 2] * f2 * f3;
        if (k == 1 || k == 2) v = -v;  // folds into FMUL neg modifier
        p4s[n] = v;
    }

    float anc[4];
    anc[0] = ac0 * ac1;
    anc[1] = ac0 * as1;
    anc[2] = as0 * ac1;
    anc[3] = as0 * as1;

    u64 V[NS];
#pragma unroll
    for (int idx = 0; idx < NS; idx++) {
        const int n = idx >> 2;
        const int m = idx & 3;
        const int k = ((n & 1) + ((n >> 1) & 1) + ((n >> 2) & 1) + ((n >> 3) & 1)) & 3;
        float mag = p4s[n] * anc[m];
        // k even -> pure real, k odd -> pure imaginary (sign already folded)
        V[idx] = (k & 1) ? pk(0.0f, mag) : pk(mag, 0.0f);
    }

    // ---- entangling layers: CNOT ring (free, via perm) + RY sweep (packed) ----
#pragma unroll
    for (int l = 0; l < NL; l++) {
#pragma unroll
        for (int w = 0; w < NQ; w++) {
            const float cc = wc[l * NQ + w];
            const float ss = ws[l * NQ + w];
            const u64 ccp  = pk(cc, cc);
            const u64 ssp  = pk(ss, ss);
            const u64 nssp = pk(-ss, -ss);
            const int tb = 1 << (5 - w);
#pragma unroll
            for (int idx = 0; idx < NS; idx++) {
                if (!(idx & tb)) {
                    const int j = idx | tb;
                    const int a  = (l == 0) ? P1.m[idx] : P2.m[idx];
                    const int bb = (l == 0) ? P1.m[j]   : P2.m[j];
                    u64 v0 = V[a], v1 = V[bb];
                    V[a]  = f2fma(nssp, v1, f2mul(ccp, v0));
                    V[bb] = f2fma(ssp,  v0, f2mul(ccp, v1));
                }
            }
        }
    }

    // ---- readout: z_w = sum_{bit_w=0} p - sum_{bit_w=1} p, p = r^2 + i^2 ----
    u64 S0[NF], S1[NF];
#pragma unroll
    for (int w = 0; w < NF; w++) { S0[w] = pk(0.0f, 0.0f); S1[w] = pk(0.0f, 0.0f); }

#pragma unroll
    for (int idx = 0; idx < NS; idx++) {
        const u64 v = V[P2.m[idx]];
#pragma unroll
        for (int w = 0; w < NF; w++) {
            if (idx & (1 << (5 - w))) S1[w] = f2fma(v, v, S1[w]);
            else                      S0[w] = f2fma(v, v, S0[w]);
        }
    }

    float4 o;
    float a0, a1, b0, b1;
    upk(S0[0], a0, a1); upk(S1[0], b0, b1); o.x = (a0 + a1) - (b0 + b1);
    upk(S0[1], a0, a1); upk(S1[1], b0, b1); o.y = (a0 + a1) - (b0 + b1);
    upk(S0[2], a0, a1); upk(S1[2], b0, b1); o.z = (a0 + a1) - (b0 + b1);
    upk(S0[3], a0, a1); upk(S1[3], b0, b1); o.w = (a0 + a1) - (b0 + b1);
    reinterpret_cast<float4*>(out)[b] = o;
}

extern "C" void kernel_launch(void* const* d_in, const int* in_sizes, int n_in,
                              void* d_out, int out_size) {
    const float* x  = (const float*)d_in[0];   // (B, 4)
    const float* w  = (const float*)d_in[1];   // (2, 6)
    const float* ab = (const float*)d_in[2];   // (2,)

    int B = in_sizes[0] / NF;
    int threads = 64;
    int blocks = B / threads;  // 65536 / 64 = 1024, exact
    qsim_kernel<<<blocks, threads>>>(x, w, ab, (float*)d_out);
}

// round 8
// speedup vs baseline: 1.3409x; 1.0201x over previous
#include <cuda_runtime.h>

#define NQ 6
#define NF 4
#define NL 2
#define NS 64

// ---------- compile-time CNOT permutation tracking ----------
__host__ __device__ constexpr int cnot_map(int i, int c, int t) {
    return (i & (1 << (5 - c))) ? (i ^ (1 << (5 - t))) : i;
}

struct Perm { int m[NS]; };

__host__ __device__ constexpr Perm identity_perm() {
    Perm p{};
    for (int i = 0; i < NS; i++) p.m[i] = i;
    return p;
}

__host__ __device__ constexpr Perm ring_perm(Perm p) {
    for (int w = 0; w < NQ; w++) {
        Perm q{};
        for (int i = 0; i < NS; i++)
            q.m[i] = p.m[cnot_map(i, w, (w + 1) % NQ)];
        p = q;
    }
    return p;
}

// ---------- packed f32x2 helpers (sm_100+) ----------
typedef unsigned long long u64;

__device__ __forceinline__ u64 pk(float lo, float hi) {
    u64 r;
    asm("mov.b64 %0, {%1, %2};" : "=l"(r) : "f"(lo), "f"(hi));
    return r;
}
__device__ __forceinline__ void upk(u64 v, float& lo, float& hi) {
    asm("mov.b64 {%0, %1}, %2;" : "=f"(lo), "=f"(hi) : "l"(v));
}
__device__ __forceinline__ u64 f2mul(u64 a, u64 b) {
    u64 d;
    asm("mul.rn.f32x2 %0, %1, %2;" : "=l"(d) : "l"(a), "l"(b));
    return d;
}
__device__ __forceinline__ u64 f2fma(u64 a, u64 b, u64 c) {
    u64 d;
    asm("fma.rn.f32x2 %0, %1, %2, %3;" : "=l"(d) : "l"(a), "l"(b), "l"(c));
    return d;
}
__device__ __forceinline__ u64 f2add(u64 a, u64 b) {
    u64 d;
    asm("add.rn.f32x2 %0, %1, %2;" : "=l"(d) : "l"(a), "l"(b));
    return d;
}

// ---------- precomputed weight data (prep kernel -> main kernel) ----------
__device__ u64   g_t[NL * NQ];    // (t, t)   t = tan(theta/2)
__device__ u64   g_nt[NL * NQ];   // (-t, -t)
__device__ float g_anc[4];        // Kronecker of ancilla RY amplitudes, x C (cos product)

__global__ void prep_kernel(const float* __restrict__ w, const float* __restrict__ ab) {
    if (threadIdx.x != 0) return;
    float C = 1.0f;
#pragma unroll
    for (int i = 0; i < NL * NQ; i++) {
        float s, c;
        __sincosf(0.5f * w[i], &s, &c);
        float t = __fdividef(s, c);
        C *= c;
        g_t[i]  = pk(t, t);
        g_nt[i] = pk(-t, -t);
    }
    float ac0, as0, ac1, as1;
    __sincosf(0.5f * ab[0], &as0, &ac0);
    __sincosf(0.5f * ab[1], &as1, &ac1);
    g_anc[0] = ac0 * ac1 * C;
    g_anc[1] = ac0 * as1 * C;
    g_anc[2] = as0 * ac1 * C;
    g_anc[3] = as0 * as1 * C;
}

// One thread = one sample. Packed state: V[idx] = (Re, Im) in one 64-bit reg pair.
__global__ void __launch_bounds__(64) qsim_kernel(const float* __restrict__ x,
                                                  float* __restrict__ out) {
    constexpr Perm P1 = ring_perm(identity_perm());  // after layer-1 CNOT ring
    constexpr Perm P2 = ring_perm(P1);               // after layer-2 CNOT ring

    const int b = blockIdx.x * blockDim.x + threadIdx.x;

    // ---- per-thread x trig ----
    float4 xv = reinterpret_cast<const float4*>(x)[b];
    float xc[NF], xs[NF];
    __sincosf(0.5f * xv.x, &xs[0], &xc[0]);
    __sincosf(0.5f * xv.y, &xs[1], &xc[1]);
    __sincosf(0.5f * xv.z, &xs[2], &xc[2]);
    __sincosf(0.5f * xv.w, &xs[3], &xc[3]);

    // ---- initial product state ----
    // RX(x)|0> per encoded qubit -> magnitude Kronecker product, phase (-i)^k,
    // k = popcount over qubits 0..3; sign folded into the magnitude.
    float p2[4];
    p2[0] = xc[0] * xc[1];
    p2[1] = xc[0] * xs[1];
    p2[2] = xs[0] * xc[1];
    p2[3] = xs[0] * xs[1];

    float p4s[16];
#pragma unroll
    for (int n = 0; n < 16; n++) {
        const int k = ((n & 1) + ((n >> 1) & 1) + ((n >> 2) & 1) + ((n >> 3) & 1)) & 3;
        float f2 = (n & 2) ? xs[2] : xc[2];
        float f3 = (n & 1) ? xs[3] : xc[3];
        float v = p2[n >> 2] * f2 * f3;
        if (k == 1 || k == 2) v = -v;
        p4s[n] = v;
    }

    // ancilla Kronecker factors, pre-scaled by C (tan-trick global cosine product)
    float anc[4];
    anc[0] = g_anc[0];
    anc[1] = g_anc[1];
    anc[2] = g_anc[2];
    anc[3] = g_anc[3];

    u64 V[NS];
#pragma unroll
    for (int idx = 0; idx < NS; idx++) {
        const int n = idx >> 2;
        const int m = idx & 3;
        const int k = ((n & 1) + ((n >> 1) & 1) + ((n >> 2) & 1) + ((n >> 3) & 1)) & 3;
        float mag = p4s[n] * anc[m];
        V[idx] = (k & 1) ? pk(0.0f, mag) : pk(mag, 0.0f);
    }

    // ---- entangling layers: CNOT ring (free via perm) + tan-form RY sweep ----
    // RY = cos * [[1,-t],[t,1]]; the cos factors are already folded into anc[].
    // Butterfly: v0' = v0 - t*v1 ; v1' = v1 + t*v0  -> 1 packed FMA per output.
#pragma unroll
    for (int l = 0; l < NL; l++) {
#pragma unroll
        for (int w = 0; w < NQ; w++) {
            const u64 tt  = g_t[l * NQ + w];
            const u64 ntt = g_nt[l * NQ + w];
            const int tb = 1 << (5 - w);
#pragma unroll
            for (int idx = 0; idx < NS; idx++) {
                if (!(idx & tb)) {
                    const int j = idx | tb;
                    const int a  = (l == 0) ? P1.m[idx] : P2.m[idx];
                    const int bb = (l == 0) ? P1.m[j]   : P2.m[j];
                    u64 v0 = V[a], v1 = V[bb];
                    V[a]  = f2fma(ntt, v1, v0);
                    V[bb] = f2fma(tt,  v0, v1);
                }
            }
        }
    }

    // ---- readout ----
    // p[idx] = (r^2, i^2) packed; first reduce over the 4 ancilla states (idx&3),
    // then a partial Walsh tree gives the 4 signed sums <Z_w>.
    u64 c16[16];
#pragma unroll
    for (int n = 0; n < 16; n++) {
        const u64 q0 = V[P2.m[4 * n + 0]];
        const u64 q1 = V[P2.m[4 * n + 1]];
        const u64 q2 = V[P2.m[4 * n + 2]];
        const u64 q3 = V[P2.m[4 * n + 3]];
        c16[n] = f2add(f2add(f2mul(q0, q0), f2mul(q1, q1)),
                       f2add(f2mul(q2, q2), f2mul(q3, q3)));
    }

    const u64 m1 = pk(-1.0f, -1.0f);   // f2sub(a,b) = fma(b, -1, a)
#define F2SUB(a, bq) f2fma((bq), m1, (a))

    // n bits: bit3 = qubit0, bit2 = qubit1, bit1 = qubit2, bit0 = qubit3
    u64 eA[8], z3s;
    {
        u64 d[8];
#pragma unroll
        for (int k = 0; k < 8; k++) {
            eA[k] = f2add(c16[2 * k], c16[2 * k + 1]);
            d[k]  = F2SUB(c16[2 * k], c16[2 * k + 1]);
        }
        z3s = f2add(f2add(f2add(d[0], d[1]), f2add(d[2], d[3])),
                    f2add(f2add(d[4], d[5]), f2add(d[6], d[7])));
    }
    u64 eB[4], z2s;
    {
        u64 d[4];
#pragma unroll
        for (int k = 0; k < 4; k++) {
            eB[k] = f2add(eA[2 * k], eA[2 * k + 1]);
            d[k]  = F2SUB(eA[2 * k], eA[2 * k + 1]);
        }
        z2s = f2add(f2add(d[0], d[1]), f2add(d[2], d[3]));
    }
    u64 eC0 = f2add(eB[0], eB[1]);
    u64 eC1 = f2add(eB[2], eB[3]);
    u64 z1s = f2add(F2SUB(eB[0], eB[1]), F2SUB(eB[2], eB[3]));
    u64 z0s = F2SUB(eC0, eC1);

    float4 o;
    float lo, hi;
    upk(z0s, lo, hi); o.x = lo + hi;
    upk(z1s, lo, hi); o.y = lo + hi;
    upk(z2s, lo, hi); o.z = lo + hi;
    upk(z3s, lo, hi); o.w = lo + hi;
    reinterpret_cast<float4*>(out)[b] = o;
}

extern "C" void kernel_launch(void* const* d_in, const int* in_sizes, int n_in,
                              void* d_out, int out_size) {
    const float* x  = (const float*)d_in[0];   // (B, 4)
    const float* w  = (const float*)d_in[1];   // (2, 6)
    const float* ab = (const float*)d_in[2];   // (2,)

    prep_kernel<<<1, 32>>>(w, ab);

    int B = in_sizes[0] / NF;
    int threads = 64;
    int blocks = B / threads;  // 1024
    qsim_kernel<<<blocks, threads>>>(x, (float*)d_out);
}